// round 14
// baseline (speedup 1.0000x reference)
#include <cuda_runtime.h>
#include <cstdint>

#define B_ 16
#define A_ 5
#define C_ 20
#define HF 19
#define WF 19
#define S_ 361           // 19*19
#define N_ 1805          // A_*S_
#define BN 28880         // B_*N_
#define PROB_ELEMS 577600  // B_*N_*C_
#define NW 57            // ceil(1805/32)
#define MROW 64          // padded words per mask row (uint2 x 32)
#define NTILE 1653       // 57*58/2 upper-triangle tiles

__constant__ float c_biases[10] = {1.08f, 1.19f, 3.42f, 4.41f, 6.63f,
                                   11.38f, 9.42f, 5.11f, 16.62f, 10.52f};

// scratch (zero-initialized; k_mask only writes words 0..56 of each 64-word
// row, so words 57..63 stay 0 forever — word 63 is the "invalid rank" pad)
__device__ float g_scores[PROB_ELEMS];                   // [b][c][n]
__device__ float g_x1[BN], g_y1[BN], g_x2[BN], g_y2[BN], g_area[BN];
__device__ unsigned g_mask[(size_t)B_ * N_ * MROW];      // [b][i][word]
__device__ unsigned long long g_order[(size_t)B_ * C_ * N_];
// per (p,chunk): words 0..31 = clamped member indices, 32..63 = sup words
__device__ unsigned g_supidx[(size_t)B_ * C_ * NW * 64];

// ---------------------------------------------------------------------------
// K1: decode boxes + scores
// ---------------------------------------------------------------------------
__global__ __launch_bounds__(128) void k_decode(const float* __restrict__ x,
                                                const float* __restrict__ iminfo,
                                                float* __restrict__ out) {
    int t = blockIdx.x * blockDim.x + threadIdx.x;
    if (t >= BN) return;
    int b = t / N_, n = t - b * N_;
    int a = n / S_, s = n - a * S_;
    int hy = s / WF, wx = s - hy * WF;
    const float* p = x + (size_t)b * (125 * S_) + s;

    float tx = p[(2 * a) * S_];
    float ty = p[(2 * a + 1) * S_];
    float tw = p[(10 + 2 * a) * S_];
    float th = p[(11 + 2 * a) * S_];
    float to = p[(20 + a) * S_];

    float sx = 1.0f / (1.0f + expf(-tx));
    float sy = 1.0f / (1.0f + expf(-ty));
    float obj = 1.0f / (1.0f + expf(-to));

    float cf[C_];
    float mx = -1e30f;
#pragma unroll
    for (int c = 0; c < C_; c++) {
        cf[c] = p[(25 + a * C_ + c) * S_];
        mx = fmaxf(mx, cf[c]);
    }
    float sum = 0.0f;
#pragma unroll
    for (int c = 0; c < C_; c++) {
        cf[c] = expf(cf[c] - mx);
        sum += cf[c];
    }
    float osc = obj / sum;

    float imh = iminfo[2 * b + 0];
    float imw = iminfo[2 * b + 1];

    float bx = (sx + (float)wx) / 19.0f * imw;
    float by = (sy + (float)hy) / 19.0f * imh;
    float bw = expf(tw) * c_biases[2 * a] / 19.0f * imw;
    float bh = expf(th) * c_biases[2 * a + 1] / 19.0f * imh;

    reinterpret_cast<float4*>(out + PROB_ELEMS)[t] = make_float4(bx, by, bw, bh);

    float hw = bw * 0.5f, hh = bh * 0.5f;
    g_x1[t] = bx - hw;
    g_x2[t] = bx + hw;
    g_y1[t] = by - hh;
    g_y2[t] = by + hh;
    g_area[t] = bw * bh;

#pragma unroll
    for (int c = 0; c < C_; c++)
        g_scores[((size_t)b * C_ + c) * N_ + n] = cf[c] * osc;
}

// ---------------------------------------------------------------------------
// K2: suppression bitmask, one warp per 32x32 tile, upper triangle + ballot.
// ---------------------------------------------------------------------------
__global__ __launch_bounds__(256) void k_mask() {
    int b = blockIdx.x;
    int warp = blockIdx.y * (blockDim.x >> 5) + (threadIdx.x >> 5);
    if (warp >= NTILE) return;
    int lane = threadIdx.x & 31;

    int rb = (int)((115.0f - sqrtf(13225.0f - 8.0f * (float)warp)) * 0.5f);
    rb = max(0, min(56, rb));
    while (rb > 0 && warp < rb * NW - (rb * (rb - 1)) / 2) rb--;
    while (warp >= (rb + 1) * NW - ((rb + 1) * rb) / 2) rb++;
    int w = rb + (warp - (rb * NW - (rb * (rb - 1)) / 2));

    int i = rb * 32 + lane;
    int gi = b * N_ + min(i, N_ - 1);
    float ix1 = g_x1[gi], iy1 = g_y1[gi], ix2 = g_x2[gi], iy2 = g_y2[gi];
    float ki = fmaf(0.45f, g_area[gi], 4.5e-10f);

    int jl = w * 32 + lane;
    int gj = b * N_ + min(jl, N_ - 1);
    float cx1 = g_x1[gj], cy1 = g_y1[gj], cx2 = g_x2[gj], cy2 = g_y2[gj];
    float ca = g_area[gj];

    unsigned bits = 0u, tbits = 0u;
    int jbase = w * 32;
#pragma unroll 8
    for (int jj = 0; jj < 32; jj++) {
        float jx1 = __shfl_sync(0xFFFFFFFFu, cx1, jj);
        float jy1 = __shfl_sync(0xFFFFFFFFu, cy1, jj);
        float jx2 = __shfl_sync(0xFFFFFFFFu, cx2, jj);
        float jy2 = __shfl_sync(0xFFFFFFFFu, cy2, jj);
        float ja  = __shfl_sync(0xFFFFFFFFu, ca, jj);
        float iw = fmaxf(fminf(ix2, jx2) - fmaxf(ix1, jx1), 0.0f);
        float ih = fmaxf(fminf(iy2, jy2) - fmaxf(iy1, jy1), 0.0f);
        float inter = iw * ih;
        bool pred = (inter * 1.45f > fmaf(0.45f, ja, ki)) && (i != jbase + jj);
        unsigned bal = __ballot_sync(0xFFFFFFFFu, pred);
        bits |= pred ? (1u << jj) : 0u;
        if (lane == jj) tbits = bal;
    }
    if (i < N_) g_mask[(size_t)(b * N_ + i) * MROW + w] = bits;
    if (w != rb && jl < N_) g_mask[(size_t)(b * N_ + jl) * MROW + rb] = tbits;
}

// ---------------------------------------------------------------------------
// K3: register bitonic sort (descending) of 2048 packed u64 keys per (b,c).
// j<=16 via shfl.bfly, j=32 thread-local, j>=64 conflict-free smem passes.
// ---------------------------------------------------------------------------
__device__ __forceinline__ unsigned long long shfl_xor_u64(unsigned long long v,
                                                           int m) {
    unsigned lo = (unsigned)v, hi = (unsigned)(v >> 32);
    lo = __shfl_xor_sync(0xFFFFFFFFu, lo, m);
    hi = __shfl_xor_sync(0xFFFFFFFFu, hi, m);
    return ((unsigned long long)hi << 32) | lo;
}
__device__ __forceinline__ unsigned long long cmp_keep(unsigned long long r,
                                                       unsigned long long o,
                                                       bool takeMax) {
    return takeMax ? (r > o ? r : o) : (r < o ? r : o);
}

__global__ __launch_bounds__(1024) void k_sort() {
    __shared__ unsigned long long sm[2048];
    int p = blockIdx.x;           // 0..319 = b*C + c
    int tid = threadIdx.x;
    int lane = tid & 31;
    int wid = tid >> 5;
    int e0 = wid * 64 + lane, e1 = e0 + 32;
    const float* sc = g_scores + (size_t)p * N_;

    unsigned long long r0 =
        (e0 < N_) ? (((unsigned long long)__float_as_uint(sc[e0]) << 32) |
                     (unsigned long long)(2047u - (unsigned)e0))
                  : 0ull;
    unsigned long long r1 =
        (e1 < N_) ? (((unsigned long long)__float_as_uint(sc[e1]) << 32) |
                     (unsigned long long)(2047u - (unsigned)e1))
                  : 0ull;

#pragma unroll
    for (int k = 2; k <= 32; k <<= 1) {
#pragma unroll
        for (int j = k >> 1; j >= 1; j >>= 1) {
            bool d0 = ((e0 & k) == 0), d1 = ((e1 & k) == 0);
            unsigned long long o0 = shfl_xor_u64(r0, j);
            unsigned long long o1 = shfl_xor_u64(r1, j);
            bool up = (lane & j) != 0;
            r0 = cmp_keep(r0, o0, d0 ^ up);
            r1 = cmp_keep(r1, o1, d1 ^ up);
        }
    }

#pragma unroll
    for (int k = 64; k <= 2048; k <<= 1) {
#pragma unroll
        for (int j = k >> 1; j >= 64; j >>= 1) {
            sm[e0] = r0;
            sm[e1] = r1;
            __syncthreads();
            unsigned long long o0 = sm[e0 ^ j];
            unsigned long long o1 = sm[e1 ^ j];
            bool d0 = ((e0 & k) == 0), d1 = ((e1 & k) == 0);
            r0 = cmp_keep(r0, o0, d0 ^ ((e0 & j) != 0));
            r1 = cmp_keep(r1, o1, d1 ^ ((e1 & j) != 0));
            __syncthreads();
        }
        {
            bool d = ((e0 & k) == 0);
            unsigned long long lo = r0 < r1 ? r0 : r1;
            unsigned long long hi = r0 < r1 ? r1 : r0;
            r0 = d ? hi : lo;
            r1 = d ? lo : hi;
        }
#pragma unroll
        for (int j = 16; j >= 1; j >>= 1) {
            bool d0 = ((e0 & k) == 0), d1 = ((e1 & k) == 0);
            unsigned long long o0 = shfl_xor_u64(r0, j);
            unsigned long long o1 = shfl_xor_u64(r1, j);
            bool up = (lane & j) != 0;
            r0 = cmp_keep(r0, o0, d0 ^ up);
            r1 = cmp_keep(r1, o1, d1 ^ up);
        }
    }

    unsigned long long* op = g_order + (size_t)p * N_;
    if (e0 < N_) op[e0] = r0;
    if (e1 < N_) op[e1] = r1;
}

// ---------------------------------------------------------------------------
// K3b: precompute per-(p,chunk) member indices + sup words (fully parallel,
// scattered-gather method — measured 13.0-13.6us at ~63% occupancy).
// ---------------------------------------------------------------------------
__global__ __launch_bounds__(128) void k_sup() {
    int p = blockIdx.x;                       // 0..319
    int t = blockIdx.y * 4 + (threadIdx.x >> 5);
    if (t >= NW) return;
    int lane = threadIdx.x & 31;
    int b = p / C_;

    const unsigned long long* __restrict__ ord = g_order + (size_t)p * N_;
    const unsigned* __restrict__ mbase = g_mask + (size_t)b * N_ * MROW;

    int rank = t * 32 + lane;
    unsigned long long key = (rank < N_) ? ord[rank] : 0ull;
    unsigned idxr = 2047u - (unsigned)key;           // 2047 for invalid
    unsigned idxc = min(idxr, (unsigned)(N_ - 1));
    unsigned wq = idxr >> 5;                         // 63 -> pad word (0)
    unsigned bmask = 1u << (idxr & 31u);

    unsigned mysup = 0u;
#pragma unroll
    for (int i = 0; i < 32; i++) {
        unsigned idxi = __shfl_sync(0xFFFFFFFFu, idxc, i);
        unsigned q = mbase[(size_t)idxi * 64u + wq];
        unsigned bal = __ballot_sync(0xFFFFFFFFu, (q & bmask) != 0u);
        if (lane == i) mysup = bal & (0xFFFFFFFEu << i);
    }

    unsigned* dst = g_supidx + ((size_t)p * NW + t) * 64u;
    dst[lane] = idxc;
    dst[32 + lane] = mysup;
}

// ---------------------------------------------------------------------------
// K4: greedy NMS. 4 warps stage the 14.6 KB sup/idx table into smem, then
// ONE warp runs the serial scan — chosen as warp (p>>2)&3 so that the 2-3
// co-resident blocks on each SM put their scan warps on DIFFERENT SMSPs
// (block ids on one SM differ by 148/296; 37,74 are 1,2 mod 4). Previously
// every scan warp was warp 0 => SMSP 0 => 2-3x issue contention.
// ---------------------------------------------------------------------------
__global__ __launch_bounds__(128, 1) void k_nms(float* __restrict__ out) {
    __shared__ unsigned s_tab[NW * 64];

    int p = blockIdx.x;                 // 0..319
    int b = p / C_, c = p - b * C_;
    int tid = threadIdx.x;
    int wid = tid >> 5;
    int lane = tid & 31;

    {
        const uint4* g4 = reinterpret_cast<const uint4*>(
            g_supidx + (size_t)p * NW * 64u);
        uint4* s4w = reinterpret_cast<uint4*>(s_tab);
#pragma unroll
        for (int k = 0; k < 8; k++) {
            int t = tid + k * 128;
            if (t < NW * 16) s4w[t] = g4[t];
        }
    }
    __syncthreads();
    if (wid != ((p >> 2) & 3)) return;   // scan warp spread across SMSPs

    const unsigned long long* __restrict__ ord = g_order + (size_t)p * N_;
    const uint2* __restrict__ mrow2 =
        reinterpret_cast<const uint2*>(g_mask) + (size_t)b * N_ * 32;
    const uint4* __restrict__ s4 = reinterpret_cast<const uint4*>(s_tab);
    float* __restrict__ op = out + (size_t)b * N_ * C_ + c;

    unsigned keepX = 0xFFFFFFFFu, keepY = 0xFFFFFFFFu;
    unsigned long long key = ord[lane];

    for (int ch = 0; ch < NW; ch++) {
        int rank = ch * 32 + lane;
        unsigned valid = (rank < N_) ? 1u : 0u;
        unsigned idxj = 2047u - (unsigned)key;
        unsigned wqj = idxj >> 5;
        unsigned bmask = 1u << (idxj & 31u);
        float scorej = __uint_as_float((unsigned)(key >> 32));

        int nrank = rank + 32;
        unsigned long long nkey = (nrank < N_) ? ord[nrank] : 0ull;

        uint2 m[32];
#pragma unroll
        for (int k = 0; k < 8; k++) {
            uint4 a = s4[ch * 16 + k];
            m[4 * k + 0] = mrow2[a.x * 32u + lane];
            m[4 * k + 1] = mrow2[a.y * 32u + lane];
            m[4 * k + 2] = mrow2[a.z * 32u + lane];
            m[4 * k + 3] = mrow2[a.w * 32u + lane];
        }
        unsigned sup[32];
#pragma unroll
        for (int k = 0; k < 8; k++) {
            uint4 a = s4[ch * 16 + 8 + k];
            sup[4 * k + 0] = a.x;
            sup[4 * k + 1] = a.y;
            sup[4 * k + 2] = a.z;
            sup[4 * k + 3] = a.w;
        }

        unsigned vx = __shfl_sync(0xFFFFFFFFu, keepX, wqj >> 1);
        unsigned vy = __shfl_sync(0xFFFFFFFFu, keepY, wqj >> 1);
        unsigned wv = (wqj & 1u) ? vy : vx;
        unsigned alive =
            __ballot_sync(0xFFFFFFFFu, (wv & bmask) != 0u && valid);

#pragma unroll
        for (int i = 0; i < 32; i++) {
            unsigned msk = (unsigned)((int)(alive << (31 - i)) >> 31);
            alive &= ~(sup[i] & msk);
        }

        unsigned cx0 = 0u, cx1 = 0u, cy0 = 0u, cy1 = 0u;
#pragma unroll
        for (int i = 0; i < 32; i += 2) {
            unsigned msk0 = (unsigned)((int)(alive << (31 - i)) >> 31);
            unsigned msk1 = (unsigned)((int)(alive << (30 - i)) >> 31);
            cx0 |= m[i].x & msk0;
            cy0 |= m[i].y & msk0;
            cx1 |= m[i + 1].x & msk1;
            cy1 |= m[i + 1].y & msk1;
        }
        keepX &= ~(cx0 | cx1);
        keepY &= ~(cy0 | cy1);

        float val = ((alive >> lane) & 1u) ? scorej : 0.0f;
        float* addr = op + (size_t)idxj * C_;
        asm volatile(
            "{ .reg .pred p; setp.ne.u32 p, %0, 0;\n"
            "  @p st.global.f32 [%1], %2; }"
            :: "r"(valid), "l"(addr), "f"(val) : "memory");

        key = nkey;
    }
}

// ---------------------------------------------------------------------------
// Launch DAG:  decode -> { mask || sort } -> sup -> nms
// ---------------------------------------------------------------------------
extern "C" void kernel_launch(void* const* d_in, const int* in_sizes, int n_in,
                              void* d_out, int out_size) {
    const float* x = (const float*)d_in[0];
    const float* iminfo = (const float*)d_in[1];
    float* out = (float*)d_out;

    static cudaStream_t s2 = nullptr;
    static cudaEvent_t eDec = nullptr, eSort = nullptr;
    if (s2 == nullptr) {
        cudaStreamCreateWithFlags(&s2, cudaStreamNonBlocking);
        cudaEventCreateWithFlags(&eDec, cudaEventDisableTiming);
        cudaEventCreateWithFlags(&eSort, cudaEventDisableTiming);
    }

    k_decode<<<(BN + 127) / 128, 128>>>(x, iminfo, out);
    cudaEventRecord(eDec, 0);

    // main stream: mask
    dim3 gm(B_, (NTILE + 7) / 8);
    k_mask<<<gm, 256>>>();

    // side stream: sort (depends only on decode)
    cudaStreamWaitEvent(s2, eDec, 0);
    k_sort<<<B_ * C_, 1024, 0, s2>>>();
    cudaEventRecord(eSort, s2);

    // join: sup needs mask (main) + sort (s2)
    cudaStreamWaitEvent(0, eSort, 0);
    dim3 gs(B_ * C_, (NW + 3) / 4);
    k_sup<<<gs, 128>>>();

    k_nms<<<B_ * C_, 128>>>(out);
}

// round 15
// speedup vs baseline: 1.0845x; 1.0845x over previous
#include <cuda_runtime.h>
#include <cstdint>

#define B_ 16
#define A_ 5
#define C_ 20
#define HF 19
#define WF 19
#define S_ 361           // 19*19
#define N_ 1805          // A_*S_
#define BN 28880         // B_*N_
#define PROB_ELEMS 577600  // B_*N_*C_
#define NW 57            // ceil(1805/32)
#define MROW 64          // padded words per mask row (uint2 x 32)
#define NTILE 1653       // 57*58/2 upper-triangle tiles

__constant__ float c_biases[10] = {1.08f, 1.19f, 3.42f, 4.41f, 6.63f,
                                   11.38f, 9.42f, 5.11f, 16.62f, 10.52f};

// scratch (zero-initialized; k_mask only writes words 0..56 of each 64-word
// row, so words 57..63 stay 0 forever — word 63 is the "invalid rank" pad)
__device__ float g_scores[PROB_ELEMS];                   // [b][c][n]
__device__ float g_x1[BN], g_y1[BN], g_x2[BN], g_y2[BN], g_area[BN];
__device__ unsigned g_mask[(size_t)B_ * N_ * MROW];      // [b][i][word]
__device__ unsigned long long g_order[(size_t)B_ * C_ * N_];
// per (p,chunk): words 0..31 = clamped member indices, 32..63 = sup words
__device__ unsigned g_supidx[(size_t)B_ * C_ * NW * 64];

// ---------------------------------------------------------------------------
// K1: decode boxes + scores
// ---------------------------------------------------------------------------
__global__ __launch_bounds__(128) void k_decode(const float* __restrict__ x,
                                                const float* __restrict__ iminfo,
                                                float* __restrict__ out) {
    int t = blockIdx.x * blockDim.x + threadIdx.x;
    if (t >= BN) return;
    int b = t / N_, n = t - b * N_;
    int a = n / S_, s = n - a * S_;
    int hy = s / WF, wx = s - hy * WF;
    const float* p = x + (size_t)b * (125 * S_) + s;

    float tx = p[(2 * a) * S_];
    float ty = p[(2 * a + 1) * S_];
    float tw = p[(10 + 2 * a) * S_];
    float th = p[(11 + 2 * a) * S_];
    float to = p[(20 + a) * S_];

    float sx = 1.0f / (1.0f + expf(-tx));
    float sy = 1.0f / (1.0f + expf(-ty));
    float obj = 1.0f / (1.0f + expf(-to));

    float cf[C_];
    float mx = -1e30f;
#pragma unroll
    for (int c = 0; c < C_; c++) {
        cf[c] = p[(25 + a * C_ + c) * S_];
        mx = fmaxf(mx, cf[c]);
    }
    float sum = 0.0f;
#pragma unroll
    for (int c = 0; c < C_; c++) {
        cf[c] = expf(cf[c] - mx);
        sum += cf[c];
    }
    float osc = obj / sum;

    float imh = iminfo[2 * b + 0];
    float imw = iminfo[2 * b + 1];

    float bx = (sx + (float)wx) / 19.0f * imw;
    float by = (sy + (float)hy) / 19.0f * imh;
    float bw = expf(tw) * c_biases[2 * a] / 19.0f * imw;
    float bh = expf(th) * c_biases[2 * a + 1] / 19.0f * imh;

    reinterpret_cast<float4*>(out + PROB_ELEMS)[t] = make_float4(bx, by, bw, bh);

    float hw = bw * 0.5f, hh = bh * 0.5f;
    g_x1[t] = bx - hw;
    g_x2[t] = bx + hw;
    g_y1[t] = by - hh;
    g_y2[t] = by + hh;
    g_area[t] = bw * bh;

#pragma unroll
    for (int c = 0; c < C_; c++)
        g_scores[((size_t)b * C_ + c) * N_ + n] = cf[c] * osc;
}

// ---------------------------------------------------------------------------
// K2: suppression bitmask, one warp per 32x32 tile, upper triangle + ballot.
// ---------------------------------------------------------------------------
__global__ __launch_bounds__(256) void k_mask() {
    int b = blockIdx.x;
    int warp = blockIdx.y * (blockDim.x >> 5) + (threadIdx.x >> 5);
    if (warp >= NTILE) return;
    int lane = threadIdx.x & 31;

    int rb = (int)((115.0f - sqrtf(13225.0f - 8.0f * (float)warp)) * 0.5f);
    rb = max(0, min(56, rb));
    while (rb > 0 && warp < rb * NW - (rb * (rb - 1)) / 2) rb--;
    while (warp >= (rb + 1) * NW - ((rb + 1) * rb) / 2) rb++;
    int w = rb + (warp - (rb * NW - (rb * (rb - 1)) / 2));

    int i = rb * 32 + lane;
    int gi = b * N_ + min(i, N_ - 1);
    float ix1 = g_x1[gi], iy1 = g_y1[gi], ix2 = g_x2[gi], iy2 = g_y2[gi];
    float ki = fmaf(0.45f, g_area[gi], 4.5e-10f);

    int jl = w * 32 + lane;
    int gj = b * N_ + min(jl, N_ - 1);
    float cx1 = g_x1[gj], cy1 = g_y1[gj], cx2 = g_x2[gj], cy2 = g_y2[gj];
    float ca = g_area[gj];

    unsigned bits = 0u, tbits = 0u;
    int jbase = w * 32;
#pragma unroll 8
    for (int jj = 0; jj < 32; jj++) {
        float jx1 = __shfl_sync(0xFFFFFFFFu, cx1, jj);
        float jy1 = __shfl_sync(0xFFFFFFFFu, cy1, jj);
        float jx2 = __shfl_sync(0xFFFFFFFFu, cx2, jj);
        float jy2 = __shfl_sync(0xFFFFFFFFu, cy2, jj);
        float ja  = __shfl_sync(0xFFFFFFFFu, ca, jj);
        float iw = fmaxf(fminf(ix2, jx2) - fmaxf(ix1, jx1), 0.0f);
        float ih = fmaxf(fminf(iy2, jy2) - fmaxf(iy1, jy1), 0.0f);
        float inter = iw * ih;
        bool pred = (inter * 1.45f > fmaf(0.45f, ja, ki)) && (i != jbase + jj);
        unsigned bal = __ballot_sync(0xFFFFFFFFu, pred);
        bits |= pred ? (1u << jj) : 0u;
        if (lane == jj) tbits = bal;
    }
    if (i < N_) g_mask[(size_t)(b * N_ + i) * MROW + w] = bits;
    if (w != rb && jl < N_) g_mask[(size_t)(b * N_ + jl) * MROW + rb] = tbits;
}

// ---------------------------------------------------------------------------
// K3: register bitonic sort (descending) of 2048 packed u64 keys per (b,c).
// j<=16 via shfl.bfly, j=32 thread-local, j>=64 conflict-free smem passes.
// ---------------------------------------------------------------------------
__device__ __forceinline__ unsigned long long shfl_xor_u64(unsigned long long v,
                                                           int m) {
    unsigned lo = (unsigned)v, hi = (unsigned)(v >> 32);
    lo = __shfl_xor_sync(0xFFFFFFFFu, lo, m);
    hi = __shfl_xor_sync(0xFFFFFFFFu, hi, m);
    return ((unsigned long long)hi << 32) | lo;
}
__device__ __forceinline__ unsigned long long cmp_keep(unsigned long long r,
                                                       unsigned long long o,
                                                       bool takeMax) {
    return takeMax ? (r > o ? r : o) : (r < o ? r : o);
}

__global__ __launch_bounds__(1024) void k_sort() {
    __shared__ unsigned long long sm[2048];
    int p = blockIdx.x;           // 0..319 = b*C + c
    int tid = threadIdx.x;
    int lane = tid & 31;
    int wid = tid >> 5;
    int e0 = wid * 64 + lane, e1 = e0 + 32;
    const float* sc = g_scores + (size_t)p * N_;

    unsigned long long r0 =
        (e0 < N_) ? (((unsigned long long)__float_as_uint(sc[e0]) << 32) |
                     (unsigned long long)(2047u - (unsigned)e0))
                  : 0ull;
    unsigned long long r1 =
        (e1 < N_) ? (((unsigned long long)__float_as_uint(sc[e1]) << 32) |
                     (unsigned long long)(2047u - (unsigned)e1))
                  : 0ull;

#pragma unroll
    for (int k = 2; k <= 32; k <<= 1) {
#pragma unroll
        for (int j = k >> 1; j >= 1; j >>= 1) {
            bool d0 = ((e0 & k) == 0), d1 = ((e1 & k) == 0);
            unsigned long long o0 = shfl_xor_u64(r0, j);
            unsigned long long o1 = shfl_xor_u64(r1, j);
            bool up = (lane & j) != 0;
            r0 = cmp_keep(r0, o0, d0 ^ up);
            r1 = cmp_keep(r1, o1, d1 ^ up);
        }
    }

#pragma unroll
    for (int k = 64; k <= 2048; k <<= 1) {
#pragma unroll
        for (int j = k >> 1; j >= 64; j >>= 1) {
            sm[e0] = r0;
            sm[e1] = r1;
            __syncthreads();
            unsigned long long o0 = sm[e0 ^ j];
            unsigned long long o1 = sm[e1 ^ j];
            bool d0 = ((e0 & k) == 0), d1 = ((e1 & k) == 0);
            r0 = cmp_keep(r0, o0, d0 ^ ((e0 & j) != 0));
            r1 = cmp_keep(r1, o1, d1 ^ ((e1 & j) != 0));
            __syncthreads();
        }
        {
            bool d = ((e0 & k) == 0);
            unsigned long long lo = r0 < r1 ? r0 : r1;
            unsigned long long hi = r0 < r1 ? r1 : r0;
            r0 = d ? hi : lo;
            r1 = d ? lo : hi;
        }
#pragma unroll
        for (int j = 16; j >= 1; j >>= 1) {
            bool d0 = ((e0 & k) == 0), d1 = ((e1 & k) == 0);
            unsigned long long o0 = shfl_xor_u64(r0, j);
            unsigned long long o1 = shfl_xor_u64(r1, j);
            bool up = (lane & j) != 0;
            r0 = cmp_keep(r0, o0, d0 ^ up);
            r1 = cmp_keep(r1, o1, d1 ^ up);
        }
    }

    unsigned long long* op = g_order + (size_t)p * N_;
    if (e0 < N_) op[e0] = r0;
    if (e1 < N_) op[e1] = r1;
}

// ---------------------------------------------------------------------------
// K3b: precompute per-(p,chunk) member indices + sup words.
// Two-phase: issue all 32 scattered loads first (MLP=32, latency fully
// pipelined), then run the 32 ballots from registers. Previously load+ballot
// were interleaved and the ballot convergence points serialized the loads.
// ---------------------------------------------------------------------------
__global__ __launch_bounds__(128) void k_sup() {
    int p = blockIdx.x;                       // 0..319
    int t = blockIdx.y * 4 + (threadIdx.x >> 5);
    if (t >= NW) return;
    int lane = threadIdx.x & 31;
    int b = p / C_;

    const unsigned long long* __restrict__ ord = g_order + (size_t)p * N_;
    const unsigned* __restrict__ mbase = g_mask + (size_t)b * N_ * MROW;

    int rank = t * 32 + lane;
    unsigned long long key = (rank < N_) ? ord[rank] : 0ull;
    unsigned idxr = 2047u - (unsigned)key;           // 2047 for invalid
    unsigned idxc = min(idxr, (unsigned)(N_ - 1));
    unsigned wq = idxr >> 5;                         // 63 -> pad word (0)
    unsigned bmask = 1u << (idxr & 31u);

    // phase 1: all loads in flight
    unsigned q[32];
#pragma unroll
    for (int i = 0; i < 32; i++) {
        unsigned idxi = __shfl_sync(0xFFFFFFFFu, idxc, i);
        q[i] = mbase[(size_t)idxi * 64u + wq];
    }
    // phase 2: ballots from registers
    unsigned mysup = 0u;
#pragma unroll
    for (int i = 0; i < 32; i++) {
        unsigned bal = __ballot_sync(0xFFFFFFFFu, (q[i] & bmask) != 0u);
        if (lane == i) mysup = bal & (0xFFFFFFFEu << i);
    }

    unsigned* dst = g_supidx + ((size_t)p * NW + t) * 64u;
    dst[lane] = idxc;
    dst[32 + lane] = mysup;
}

// ---------------------------------------------------------------------------
// K4: greedy NMS (R7/R13 version, measured 50us — do not perturb).
// 4 warps stage the 14.6 KB sup/idx table into smem, warp 0 runs the scan.
// ---------------------------------------------------------------------------
__global__ __launch_bounds__(128, 1) void k_nms(float* __restrict__ out) {
    __shared__ unsigned s_tab[NW * 64];

    int p = blockIdx.x;                 // 0..319
    int b = p / C_, c = p - b * C_;
    int tid = threadIdx.x;
    int lane = tid & 31;

    {
        const uint4* g4 = reinterpret_cast<const uint4*>(
            g_supidx + (size_t)p * NW * 64u);
        uint4* s4w = reinterpret_cast<uint4*>(s_tab);
#pragma unroll
        for (int k = 0; k < 8; k++) {
            int t = tid + k * 128;
            if (t < NW * 16) s4w[t] = g4[t];
        }
    }
    __syncthreads();
    if (tid >= 32) return;

    const unsigned long long* __restrict__ ord = g_order + (size_t)p * N_;
    const uint2* __restrict__ mrow2 =
        reinterpret_cast<const uint2*>(g_mask) + (size_t)b * N_ * 32;
    const uint4* __restrict__ s4 = reinterpret_cast<const uint4*>(s_tab);
    float* __restrict__ op = out + (size_t)b * N_ * C_ + c;

    unsigned keepX = 0xFFFFFFFFu, keepY = 0xFFFFFFFFu;
    unsigned long long key = ord[lane];

    for (int ch = 0; ch < NW; ch++) {
        int rank = ch * 32 + lane;
        unsigned valid = (rank < N_) ? 1u : 0u;
        unsigned idxj = 2047u - (unsigned)key;
        unsigned wqj = idxj >> 5;
        unsigned bmask = 1u << (idxj & 31u);
        float scorej = __uint_as_float((unsigned)(key >> 32));

        int nrank = rank + 32;
        unsigned long long nkey = (nrank < N_) ? ord[nrank] : 0ull;

        uint2 m[32];
#pragma unroll
        for (int k = 0; k < 8; k++) {
            uint4 a = s4[ch * 16 + k];
            m[4 * k + 0] = mrow2[a.x * 32u + lane];
            m[4 * k + 1] = mrow2[a.y * 32u + lane];
            m[4 * k + 2] = mrow2[a.z * 32u + lane];
            m[4 * k + 3] = mrow2[a.w * 32u + lane];
        }
        unsigned sup[32];
#pragma unroll
        for (int k = 0; k < 8; k++) {
            uint4 a = s4[ch * 16 + 8 + k];
            sup[4 * k + 0] = a.x;
            sup[4 * k + 1] = a.y;
            sup[4 * k + 2] = a.z;
            sup[4 * k + 3] = a.w;
        }

        unsigned vx = __shfl_sync(0xFFFFFFFFu, keepX, wqj >> 1);
        unsigned vy = __shfl_sync(0xFFFFFFFFu, keepY, wqj >> 1);
        unsigned wv = (wqj & 1u) ? vy : vx;
        unsigned alive =
            __ballot_sync(0xFFFFFFFFu, (wv & bmask) != 0u && valid);

#pragma unroll
        for (int i = 0; i < 32; i++) {
            unsigned msk = (unsigned)((int)(alive << (31 - i)) >> 31);
            alive &= ~(sup[i] & msk);
        }

        unsigned cx0 = 0u, cx1 = 0u, cy0 = 0u, cy1 = 0u;
#pragma unroll
        for (int i = 0; i < 32; i += 2) {
            unsigned msk0 = (unsigned)((int)(alive << (31 - i)) >> 31);
            unsigned msk1 = (unsigned)((int)(alive << (30 - i)) >> 31);
            cx0 |= m[i].x & msk0;
            cy0 |= m[i].y & msk0;
            cx1 |= m[i + 1].x & msk1;
            cy1 |= m[i + 1].y & msk1;
        }
        keepX &= ~(cx0 | cx1);
        keepY &= ~(cy0 | cy1);

        float val = ((alive >> lane) & 1u) ? scorej : 0.0f;
        float* addr = op + (size_t)idxj * C_;
        asm volatile(
            "{ .reg .pred p; setp.ne.u32 p, %0, 0;\n"
            "  @p st.global.f32 [%1], %2; }"
            :: "r"(valid), "l"(addr), "f"(val) : "memory");

        key = nkey;
    }
}

// ---------------------------------------------------------------------------
// Launch DAG:  decode -> { mask || sort } -> sup -> nms
// ---------------------------------------------------------------------------
extern "C" void kernel_launch(void* const* d_in, const int* in_sizes, int n_in,
                              void* d_out, int out_size) {
    const float* x = (const float*)d_in[0];
    const float* iminfo = (const float*)d_in[1];
    float* out = (float*)d_out;

    static cudaStream_t s2 = nullptr;
    static cudaEvent_t eDec = nullptr, eSort = nullptr;
    if (s2 == nullptr) {
        cudaStreamCreateWithFlags(&s2, cudaStreamNonBlocking);
        cudaEventCreateWithFlags(&eDec, cudaEventDisableTiming);
        cudaEventCreateWithFlags(&eSort, cudaEventDisableTiming);
    }

    k_decode<<<(BN + 127) / 128, 128>>>(x, iminfo, out);
    cudaEventRecord(eDec, 0);

    // main stream: mask
    dim3 gm(B_, (NTILE + 7) / 8);
    k_mask<<<gm, 256>>>();

    // side stream: sort (depends only on decode)
    cudaStreamWaitEvent(s2, eDec, 0);
    k_sort<<<B_ * C_, 1024, 0, s2>>>();
    cudaEventRecord(eSort, s2);

    // join: sup needs mask (main) + sort (s2)
    cudaStreamWaitEvent(0, eSort, 0);
    dim3 gs(B_ * C_, (NW + 3) / 4);
    k_sup<<<gs, 128>>>();

    k_nms<<<B_ * C_, 128>>>(out);
}

// round 16
// speedup vs baseline: 1.1272x; 1.0393x over previous
#include <cuda_runtime.h>
#include <cstdint>

#define B_ 16
#define A_ 5
#define C_ 20
#define HF 19
#define WF 19
#define S_ 361           // 19*19
#define N_ 1805          // A_*S_
#define BN 28880         // B_*N_
#define PROB_ELEMS 577600  // B_*N_*C_
#define NW 57            // ceil(1805/32)
#define MROW 64          // padded words per mask row (uint2 x 32)

__constant__ float c_biases[10] = {1.08f, 1.19f, 3.42f, 4.41f, 6.63f,
                                   11.38f, 9.42f, 5.11f, 16.62f, 10.52f};

// scratch (zero-initialized; k_mask only writes words 0..56 of each 64-word
// row, so words 57..63 stay 0 forever — word 63 is the "invalid rank" pad)
__device__ float g_scores[PROB_ELEMS];                   // [b][c][n]
__device__ float g_x1[BN], g_y1[BN], g_x2[BN], g_y2[BN], g_area[BN];
__device__ unsigned g_mask[(size_t)B_ * N_ * MROW];      // [b][i][word]
__device__ unsigned long long g_order[(size_t)B_ * C_ * N_];
// per (p,chunk): words 0..31 = clamped member indices, 32..63 = sup words
__device__ unsigned g_supidx[(size_t)B_ * C_ * NW * 64];

// ---------------------------------------------------------------------------
// K1: decode boxes + scores
// ---------------------------------------------------------------------------
__global__ __launch_bounds__(128) void k_decode(const float* __restrict__ x,
                                                const float* __restrict__ iminfo,
                                                float* __restrict__ out) {
    int t = blockIdx.x * blockDim.x + threadIdx.x;
    if (t >= BN) return;
    int b = t / N_, n = t - b * N_;
    int a = n / S_, s = n - a * S_;
    int hy = s / WF, wx = s - hy * WF;
    const float* p = x + (size_t)b * (125 * S_) + s;

    float tx = p[(2 * a) * S_];
    float ty = p[(2 * a + 1) * S_];
    float tw = p[(10 + 2 * a) * S_];
    float th = p[(11 + 2 * a) * S_];
    float to = p[(20 + a) * S_];

    float sx = 1.0f / (1.0f + expf(-tx));
    float sy = 1.0f / (1.0f + expf(-ty));
    float obj = 1.0f / (1.0f + expf(-to));

    float cf[C_];
    float mx = -1e30f;
#pragma unroll
    for (int c = 0; c < C_; c++) {
        cf[c] = p[(25 + a * C_ + c) * S_];
        mx = fmaxf(mx, cf[c]);
    }
    float sum = 0.0f;
#pragma unroll
    for (int c = 0; c < C_; c++) {
        cf[c] = expf(cf[c] - mx);
        sum += cf[c];
    }
    float osc = obj / sum;

    float imh = iminfo[2 * b + 0];
    float imw = iminfo[2 * b + 1];

    float bx = (sx + (float)wx) / 19.0f * imw;
    float by = (sy + (float)hy) / 19.0f * imh;
    float bw = expf(tw) * c_biases[2 * a] / 19.0f * imw;
    float bh = expf(th) * c_biases[2 * a + 1] / 19.0f * imh;

    reinterpret_cast<float4*>(out + PROB_ELEMS)[t] = make_float4(bx, by, bw, bh);

    float hw = bw * 0.5f, hh = bh * 0.5f;
    g_x1[t] = bx - hw;
    g_x2[t] = bx + hw;
    g_y1[t] = by - hh;
    g_y2[t] = by + hh;
    g_area[t] = bw * bh;

#pragma unroll
    for (int c = 0; c < C_; c++)
        g_scores[((size_t)b * C_ + c) * N_ + n] = cf[c] * osc;
}

// ---------------------------------------------------------------------------
// K2: suppression bitmask, 4 row-blocks per warp (j-broadcast amortized).
// Warp handles rows (4g..4g+3)*32 x col-block w, upper triangle (rb <= w).
// 5 SHFLs per step shared across 4 row-blocks; ballot-transpose per block.
// Per-pair FP expressions identical to the 1-row version (same g_mask bits).
// ---------------------------------------------------------------------------
__global__ __launch_bounds__(256) void k_mask() {
    int b = blockIdx.x;
    int w = blockIdx.y;                            // column block 0..56
    int g = blockIdx.z * 8 + (threadIdx.x >> 5);   // row group 0..15
    int lane = threadIdx.x & 31;
    int rb0 = g * 4;
    if (rb0 > w) return;

    int jl = w * 32 + lane;
    int gj = b * N_ + min(jl, N_ - 1);
    float cx1 = g_x1[gj], cy1 = g_y1[gj], cx2 = g_x2[gj], cy2 = g_y2[gj];
    float ca = g_area[gj];

    float rx1[4], ry1[4], rx2[4], ry2[4], ki[4];
    int irow[4];
#pragma unroll
    for (int k = 0; k < 4; k++) {
        int i = (rb0 + k) * 32 + lane;
        irow[k] = i;
        int gi = b * N_ + min(i, N_ - 1);
        rx1[k] = g_x1[gi];
        ry1[k] = g_y1[gi];
        rx2[k] = g_x2[gi];
        ry2[k] = g_y2[gi];
        ki[k] = fmaf(0.45f, g_area[gi], 4.5e-10f);
    }

    unsigned bits[4] = {0u, 0u, 0u, 0u};
    unsigned tbits[4] = {0u, 0u, 0u, 0u};
    int jbase = w * 32;
#pragma unroll 4
    for (int jj = 0; jj < 32; jj++) {
        float jx1 = __shfl_sync(0xFFFFFFFFu, cx1, jj);
        float jy1 = __shfl_sync(0xFFFFFFFFu, cy1, jj);
        float jx2 = __shfl_sync(0xFFFFFFFFu, cx2, jj);
        float jy2 = __shfl_sync(0xFFFFFFFFu, cy2, jj);
        float ja  = __shfl_sync(0xFFFFFFFFu, ca, jj);
#pragma unroll
        for (int k = 0; k < 4; k++) {
            float iw = fmaxf(fminf(rx2[k], jx2) - fmaxf(rx1[k], jx1), 0.0f);
            float ih = fmaxf(fminf(ry2[k], jy2) - fmaxf(ry1[k], jy1), 0.0f);
            float inter = iw * ih;
            bool pred = (inter * 1.45f > fmaf(0.45f, ja, ki[k])) &&
                        (irow[k] != jbase + jj);
            unsigned bal = __ballot_sync(0xFFFFFFFFu, pred);
            bits[k] |= pred ? (1u << jj) : 0u;
            if (lane == jj) tbits[k] = bal;
        }
    }

#pragma unroll
    for (int k = 0; k < 4; k++) {
        int rb = rb0 + k;
        if (rb > w) break;
        if (irow[k] < N_)
            g_mask[(size_t)(b * N_ + irow[k]) * MROW + w] = bits[k];
        if (w != rb && jl < N_)
            g_mask[(size_t)(b * N_ + jl) * MROW + rb] = tbits[k];
    }
}

// ---------------------------------------------------------------------------
// K3: register bitonic sort (descending) of 2048 packed u64 keys per (b,c).
// j<=16 via shfl.bfly, j=32 thread-local, j>=64 conflict-free smem passes.
// ---------------------------------------------------------------------------
__device__ __forceinline__ unsigned long long shfl_xor_u64(unsigned long long v,
                                                           int m) {
    unsigned lo = (unsigned)v, hi = (unsigned)(v >> 32);
    lo = __shfl_xor_sync(0xFFFFFFFFu, lo, m);
    hi = __shfl_xor_sync(0xFFFFFFFFu, hi, m);
    return ((unsigned long long)hi << 32) | lo;
}
__device__ __forceinline__ unsigned long long cmp_keep(unsigned long long r,
                                                       unsigned long long o,
                                                       bool takeMax) {
    return takeMax ? (r > o ? r : o) : (r < o ? r : o);
}

__global__ __launch_bounds__(1024) void k_sort() {
    __shared__ unsigned long long sm[2048];
    int p = blockIdx.x;           // 0..319 = b*C + c
    int tid = threadIdx.x;
    int lane = tid & 31;
    int wid = tid >> 5;
    int e0 = wid * 64 + lane, e1 = e0 + 32;
    const float* sc = g_scores + (size_t)p * N_;

    unsigned long long r0 =
        (e0 < N_) ? (((unsigned long long)__float_as_uint(sc[e0]) << 32) |
                     (unsigned long long)(2047u - (unsigned)e0))
                  : 0ull;
    unsigned long long r1 =
        (e1 < N_) ? (((unsigned long long)__float_as_uint(sc[e1]) << 32) |
                     (unsigned long long)(2047u - (unsigned)e1))
                  : 0ull;

#pragma unroll
    for (int k = 2; k <= 32; k <<= 1) {
#pragma unroll
        for (int j = k >> 1; j >= 1; j >>= 1) {
            bool d0 = ((e0 & k) == 0), d1 = ((e1 & k) == 0);
            unsigned long long o0 = shfl_xor_u64(r0, j);
            unsigned long long o1 = shfl_xor_u64(r1, j);
            bool up = (lane & j) != 0;
            r0 = cmp_keep(r0, o0, d0 ^ up);
            r1 = cmp_keep(r1, o1, d1 ^ up);
        }
    }

#pragma unroll
    for (int k = 64; k <= 2048; k <<= 1) {
#pragma unroll
        for (int j = k >> 1; j >= 64; j >>= 1) {
            sm[e0] = r0;
            sm[e1] = r1;
            __syncthreads();
            unsigned long long o0 = sm[e0 ^ j];
            unsigned long long o1 = sm[e1 ^ j];
            bool d0 = ((e0 & k) == 0), d1 = ((e1 & k) == 0);
            r0 = cmp_keep(r0, o0, d0 ^ ((e0 & j) != 0));
            r1 = cmp_keep(r1, o1, d1 ^ ((e1 & j) != 0));
            __syncthreads();
        }
        {
            bool d = ((e0 & k) == 0);
            unsigned long long lo = r0 < r1 ? r0 : r1;
            unsigned long long hi = r0 < r1 ? r1 : r0;
            r0 = d ? hi : lo;
            r1 = d ? lo : hi;
        }
#pragma unroll
        for (int j = 16; j >= 1; j >>= 1) {
            bool d0 = ((e0 & k) == 0), d1 = ((e1 & k) == 0);
            unsigned long long o0 = shfl_xor_u64(r0, j);
            unsigned long long o1 = shfl_xor_u64(r1, j);
            bool up = (lane & j) != 0;
            r0 = cmp_keep(r0, o0, d0 ^ up);
            r1 = cmp_keep(r1, o1, d1 ^ up);
        }
    }

    unsigned long long* op = g_order + (size_t)p * N_;
    if (e0 < N_) op[e0] = r0;
    if (e1 < N_) op[e1] = r1;
}

// ---------------------------------------------------------------------------
// K3b: precompute per-(p,chunk) member indices + sup words (two-phase).
// ---------------------------------------------------------------------------
__global__ __launch_bounds__(128) void k_sup() {
    int p = blockIdx.x;                       // 0..319
    int t = blockIdx.y * 4 + (threadIdx.x >> 5);
    if (t >= NW) return;
    int lane = threadIdx.x & 31;
    int b = p / C_;

    const unsigned long long* __restrict__ ord = g_order + (size_t)p * N_;
    const unsigned* __restrict__ mbase = g_mask + (size_t)b * N_ * MROW;

    int rank = t * 32 + lane;
    unsigned long long key = (rank < N_) ? ord[rank] : 0ull;
    unsigned idxr = 2047u - (unsigned)key;           // 2047 for invalid
    unsigned idxc = min(idxr, (unsigned)(N_ - 1));
    unsigned wq = idxr >> 5;                         // 63 -> pad word (0)
    unsigned bmask = 1u << (idxr & 31u);

    unsigned q[32];
#pragma unroll
    for (int i = 0; i < 32; i++) {
        unsigned idxi = __shfl_sync(0xFFFFFFFFu, idxc, i);
        q[i] = mbase[(size_t)idxi * 64u + wq];
    }
    unsigned mysup = 0u;
#pragma unroll
    for (int i = 0; i < 32; i++) {
        unsigned bal = __ballot_sync(0xFFFFFFFFu, (q[i] & bmask) != 0u);
        if (lane == i) mysup = bal & (0xFFFFFFFEu << i);
    }

    unsigned* dst = g_supidx + ((size_t)p * NW + t) * 64u;
    dst[lane] = idxc;
    dst[32 + lane] = mysup;
}

// ---------------------------------------------------------------------------
// K4: greedy NMS (R7/R13 version, measured 50us — do not perturb).
// 4 warps stage the 14.6 KB sup/idx table into smem, warp 0 runs the scan.
// ---------------------------------------------------------------------------
__global__ __launch_bounds__(128, 1) void k_nms(float* __restrict__ out) {
    __shared__ unsigned s_tab[NW * 64];

    int p = blockIdx.x;                 // 0..319
    int b = p / C_, c = p - b * C_;
    int tid = threadIdx.x;
    int lane = tid & 31;

    {
        const uint4* g4 = reinterpret_cast<const uint4*>(
            g_supidx + (size_t)p * NW * 64u);
        uint4* s4w = reinterpret_cast<uint4*>(s_tab);
#pragma unroll
        for (int k = 0; k < 8; k++) {
            int t = tid + k * 128;
            if (t < NW * 16) s4w[t] = g4[t];
        }
    }
    __syncthreads();
    if (tid >= 32) return;

    const unsigned long long* __restrict__ ord = g_order + (size_t)p * N_;
    const uint2* __restrict__ mrow2 =
        reinterpret_cast<const uint2*>(g_mask) + (size_t)b * N_ * 32;
    const uint4* __restrict__ s4 = reinterpret_cast<const uint4*>(s_tab);
    float* __restrict__ op = out + (size_t)b * N_ * C_ + c;

    unsigned keepX = 0xFFFFFFFFu, keepY = 0xFFFFFFFFu;
    unsigned long long key = ord[lane];

    for (int ch = 0; ch < NW; ch++) {
        int rank = ch * 32 + lane;
        unsigned valid = (rank < N_) ? 1u : 0u;
        unsigned idxj = 2047u - (unsigned)key;
        unsigned wqj = idxj >> 5;
        unsigned bmask = 1u << (idxj & 31u);
        float scorej = __uint_as_float((unsigned)(key >> 32));

        int nrank = rank + 32;
        unsigned long long nkey = (nrank < N_) ? ord[nrank] : 0ull;

        uint2 m[32];
#pragma unroll
        for (int k = 0; k < 8; k++) {
            uint4 a = s4[ch * 16 + k];
            m[4 * k + 0] = mrow2[a.x * 32u + lane];
            m[4 * k + 1] = mrow2[a.y * 32u + lane];
            m[4 * k + 2] = mrow2[a.z * 32u + lane];
            m[4 * k + 3] = mrow2[a.w * 32u + lane];
        }
        unsigned sup[32];
#pragma unroll
        for (int k = 0; k < 8; k++) {
            uint4 a = s4[ch * 16 + 8 + k];
            sup[4 * k + 0] = a.x;
            sup[4 * k + 1] = a.y;
            sup[4 * k + 2] = a.z;
            sup[4 * k + 3] = a.w;
        }

        unsigned vx = __shfl_sync(0xFFFFFFFFu, keepX, wqj >> 1);
        unsigned vy = __shfl_sync(0xFFFFFFFFu, keepY, wqj >> 1);
        unsigned wv = (wqj & 1u) ? vy : vx;
        unsigned alive =
            __ballot_sync(0xFFFFFFFFu, (wv & bmask) != 0u && valid);

#pragma unroll
        for (int i = 0; i < 32; i++) {
            unsigned msk = (unsigned)((int)(alive << (31 - i)) >> 31);
            alive &= ~(sup[i] & msk);
        }

        unsigned cx0 = 0u, cx1 = 0u, cy0 = 0u, cy1 = 0u;
#pragma unroll
        for (int i = 0; i < 32; i += 2) {
            unsigned msk0 = (unsigned)((int)(alive << (31 - i)) >> 31);
            unsigned msk1 = (unsigned)((int)(alive << (30 - i)) >> 31);
            cx0 |= m[i].x & msk0;
            cy0 |= m[i].y & msk0;
            cx1 |= m[i + 1].x & msk1;
            cy1 |= m[i + 1].y & msk1;
        }
        keepX &= ~(cx0 | cx1);
        keepY &= ~(cy0 | cy1);

        float val = ((alive >> lane) & 1u) ? scorej : 0.0f;
        float* addr = op + (size_t)idxj * C_;
        asm volatile(
            "{ .reg .pred p; setp.ne.u32 p, %0, 0;\n"
            "  @p st.global.f32 [%1], %2; }"
            :: "r"(valid), "l"(addr), "f"(val) : "memory");

        key = nkey;
    }
}

// ---------------------------------------------------------------------------
// Launch DAG:  decode -> { mask || sort } -> sup -> nms
// ---------------------------------------------------------------------------
extern "C" void kernel_launch(void* const* d_in, const int* in_sizes, int n_in,
                              void* d_out, int out_size) {
    const float* x = (const float*)d_in[0];
    const float* iminfo = (const float*)d_in[1];
    float* out = (float*)d_out;

    static cudaStream_t s2 = nullptr;
    static cudaEvent_t eDec = nullptr, eSort = nullptr;
    if (s2 == nullptr) {
        cudaStreamCreateWithFlags(&s2, cudaStreamNonBlocking);
        cudaEventCreateWithFlags(&eDec, cudaEventDisableTiming);
        cudaEventCreateWithFlags(&eSort, cudaEventDisableTiming);
    }

    k_decode<<<(BN + 127) / 128, 128>>>(x, iminfo, out);
    cudaEventRecord(eDec, 0);

    // main stream: mask (4-row multiplexed triangle)
    dim3 gm(B_, NW, 2);
    k_mask<<<gm, 256>>>();

    // side stream: sort (depends only on decode)
    cudaStreamWaitEvent(s2, eDec, 0);
    k_sort<<<B_ * C_, 1024, 0, s2>>>();
    cudaEventRecord(eSort, s2);

    // join: sup needs mask (main) + sort (s2)
    cudaStreamWaitEvent(0, eSort, 0);
    dim3 gs(B_ * C_, (NW + 3) / 4);
    k_sup<<<gs, 128>>>();

    k_nms<<<B_ * C_, 128>>>(out);
}